// round 15
// baseline (speedup 1.0000x reference)
#include <cuda_runtime.h>
#include <cuda_fp16.h>
#include <math.h>
#include <cstdint>

// ---------------- problem constants ----------------
constexpr int T    = 2048;
constexpr int H    = 1024;
constexpr int IDIM = 2816;
constexpr int E    = 8;
constexpr int TOPK = 2;

constexpr int BMT = 128;
constexpr int MAX_SLOTS = T * TOPK + E * BMT;  // 5120
constexpr int RS   = 40;  // BK=32 row stride (halfs)
constexpr int RS64 = 72;  // BK=64 row stride (halfs), 144B

constexpr size_t WELEMS = (size_t)E * IDIM * H;
constexpr int WN4 = (int)(WELEMS / 4);
constexpr int XN4 = T * H / 4;

// ---------------- scratch ----------------
__device__ int   g_off[E + 1];
__device__ int   g_slot_token[MAX_SLOTS];
__device__ float g_slot_wt[MAX_SLOTS];
__device__ int   g_top_id[T * TOPK];
__device__ float g_top_w[T * TOPK];

__device__ __align__(16) __half g_w1f[WELEMS];
__device__ __align__(16) __half g_w3f[WELEMS];
__device__ __align__(16) __half g_w2f[WELEMS];
__device__ __align__(16) __half g_xf[T * H];
__device__ __align__(16) __half g_hf[(size_t)MAX_SLOTS * IDIM];

// ---------------- PTX helpers ----------------
__device__ __forceinline__ uint32_t smem_u32(const void* p) {
    uint32_t a;
    asm("{ .reg .u64 t; cvta.to.shared.u64 t, %1; cvt.u32.u64 %0, t; }" : "=r"(a) : "l"(p));
    return a;
}
__device__ __forceinline__ void cp16(uint32_t dst, const void* src) {
    asm volatile("cp.async.cg.shared.global [%0], [%1], 16;" :: "r"(dst), "l"(src));
}
#define CP_COMMIT() asm volatile("cp.async.commit_group;" ::: "memory")
#define CP_WAIT0()  asm volatile("cp.async.wait_group 0;" ::: "memory")
#define CP_WAIT2()  asm volatile("cp.async.wait_group 2;" ::: "memory")

__device__ __forceinline__ void ldsm4(uint32_t r[4], uint32_t addr) {
    asm volatile("ldmatrix.sync.aligned.m8n8.x4.shared.b16 {%0,%1,%2,%3}, [%4];"
        : "=r"(r[0]), "=r"(r[1]), "=r"(r[2]), "=r"(r[3]) : "r"(addr));
}
__device__ __forceinline__ void mma_f16(float d[4], const uint32_t a[4], const uint32_t b[2]) {
    asm volatile(
        "mma.sync.aligned.m16n8k16.row.col.f32.f16.f16.f32 "
        "{%0,%1,%2,%3}, {%4,%5,%6,%7}, {%8,%9}, {%0,%1,%2,%3};"
        : "+f"(d[0]), "+f"(d[1]), "+f"(d[2]), "+f"(d[3])
        : "r"(a[0]), "r"(a[1]), "r"(a[2]), "r"(a[3]), "r"(b[0]), "r"(b[1]));
}
__device__ __forceinline__ uint32_t pack2h(float a, float b) {
    __half2 v;
    v.x = __float2half_rn(a);
    v.y = __float2half_rn(b);
    return *reinterpret_cast<uint32_t*>(&v);
}
__device__ __forceinline__ float silu(float g) { return g / (1.0f + __expf(-g)); }

// ---------------- launch 0: init + route ----------------
__global__ void init_route_kernel(const float* __restrict__ logits) {
    int i = blockIdx.x * blockDim.x + threadIdx.x;
    if (i < MAX_SLOTS) g_slot_token[i] = -1;
    if (i >= T) return;
    const float* lg = logits + (size_t)i * E;
    float l[E];
#pragma unroll
    for (int e = 0; e < E; e++) l[e] = lg[e];
    int a = 0; float la = l[0];
#pragma unroll
    for (int e = 1; e < E; e++) if (l[e] > la) { la = l[e]; a = e; }
    int b = -1; float lb = -INFINITY;
#pragma unroll
    for (int e = 0; e < E; e++) if (e != a && l[e] > lb) { lb = l[e]; b = e; }
    float w0 = 1.0f / (1.0f + expf(lb - la));
    g_top_id[i * 2 + 0] = a; g_top_w[i * 2 + 0] = w0;
    g_top_id[i * 2 + 1] = b; g_top_w[i * 2 + 1] = 1.0f - w0;
}

// ---------------- launch 1: count + scan + assign ----------------
__global__ void scan_assign_kernel() {
    __shared__ int cnt[E];
    __shared__ int cur[E];
    int tid = threadIdx.x;
    if (tid < E) cnt[tid] = 0;
    __syncthreads();
    for (int i = tid; i < T * TOPK; i += blockDim.x)
        atomicAdd(&cnt[g_top_id[i]], 1);
    __syncthreads();
    if (tid == 0) {
        int off = 0;
        for (int e = 0; e < E; e++) {
            g_off[e] = off; cur[e] = off;
            off += ((cnt[e] + BMT - 1) / BMT) * BMT;
        }
        g_off[E] = off;
    }
    __syncthreads();
    for (int i = tid; i < T * TOPK; i += blockDim.x) {
        int e = g_top_id[i];
        int pos = atomicAdd(&cur[e], 1);
        g_slot_token[pos] = i >> 1;
        g_slot_wt[pos] = g_top_w[i];
    }
}

// ---------------- launch 2: merged fp32->fp16 converter ----------------
constexpr int WB = WN4 / 256;
constexpr int XB = XN4 / 256;
__device__ __forceinline__ void cvt_single(const float4* __restrict__ src, __half* dst, int b) {
    int i = b * 256 + threadIdx.x;
    float4 v = src[i];
    reinterpret_cast<uint2*>(dst)[i] = make_uint2(pack2h(v.x, v.y), pack2h(v.z, v.w));
}
__global__ void cvt_all_kernel(const float4* __restrict__ W1, const float4* __restrict__ W3,
                               const float4* __restrict__ W2, const float4* __restrict__ x) {
    int b = blockIdx.x;
    if      (b < WB)          cvt_single(W1, g_w1f, b);
    else if (b < 2 * WB)      cvt_single(W3, g_w3f, b - WB);
    else if (b < 3 * WB)      cvt_single(W2, g_w2f, b - 2 * WB);
    else                      cvt_single(x, g_xf, b - 3 * WB);
}

__global__ void zero_out_kernel(float4* out) {
    out[blockIdx.x * 256 + threadIdx.x] = make_float4(0.f, 0.f, 0.f, 0.f);
}

// ---------------- GEMM1: h = silu(x W1^T) * (x W3^T) ----------------
// CTA 128M x 64N, 8 warps (32x32), BK=64, 2-stage double buffer, 3 CTAs/SM.
// Coalesced copies (R13 pattern). stage rows: A[128] G[64] U[64], row RS64 halfs.
constexpr int G1_A = 0, G1_G = 128 * RS64, G1_U = 192 * RS64;
constexpr uint32_t G1_STAGE_BYTES = 256 * RS64 * 2;   // 36864
constexpr size_t SMEM1 = 2 * (size_t)G1_STAGE_BYTES;  // 73728/CTA -> 3 CTAs/SM (221KB)

__global__ __launch_bounds__(256, 3)
void gemm1_kernel() {
    extern __shared__ __align__(16) char dsm[];
    uint32_t smemB = smem_u32(dsm);

    int mbase = blockIdx.y * 128;
    int nbase = blockIdx.x * 64;
    if (mbase >= g_off[E]) return;
    int e = 0;
    while (e < E && !(mbase >= g_off[e] && mbase < g_off[e + 1])) e++;

    int tid = threadIdx.x, lid = tid & 31, wid = tid >> 5;
    int wm = wid & 3, wn = wid >> 2;

    int r0 = tid >> 3, cch = tid & 7;
    int tk[4];
#pragma unroll
    for (int j = 0; j < 4; j++) {
        int t = g_slot_token[mbase + r0 + 32 * j];
        tk[j] = (t < 0) ? 0 : t;
    }
    const __half* gp = g_w1f + ((size_t)e * IDIM + nbase + r0) * H + cch * 8;
    const __half* up = g_w3f + ((size_t)e * IDIM + nbase + r0) * H + cch * 8;

    uint32_t rdst = (uint32_t)(r0 * RS64 * 2 + cch * 16);

    auto issue = [&](int s, int k0) {
        uint32_t sb = smemB + (uint32_t)s * G1_STAGE_BYTES + rdst;
#pragma unroll
        for (int j = 0; j < 4; j++)
            cp16(sb + (uint32_t)(32 * j * RS64 * 2),
                 g_xf + (size_t)tk[j] * H + k0 + cch * 8);
#pragma unroll
        for (int j = 0; j < 2; j++)
            cp16(sb + (uint32_t)((128 + 32 * j) * RS64 * 2), gp + (size_t)(32 * j) * H + k0);
#pragma unroll
        for (int j = 0; j < 2; j++)
            cp16(sb + (uint32_t)((192 + 32 * j) * RS64 * 2), up + (size_t)(32 * j) * H + k0);
    };

    int a_lr = (lid & 7) + ((lid >> 3) & 1) * 8, a_lk = ((lid >> 4) & 1) * 8;
    int b_lr = (lid & 7) + ((lid >> 4) & 1) * 8, b_lk = ((lid >> 3) & 1) * 8;

    float dg[2][4][4] = {}, du[2][4][4] = {};

    issue(0, 0); CP_COMMIT();

    constexpr int NCH = H / 64; // 16
    for (int c = 0; c < NCH; c++) {
        CP_WAIT0();                  // stage (c&1) fully landed
        __syncthreads();             // all warps done with stage ((c+1)&1) from chunk c-1
        if (c + 1 < NCH) { issue((c + 1) & 1, (c + 1) * 64); CP_COMMIT(); }
        uint32_t bb = smemB + (uint32_t)(c & 1) * G1_STAGE_BYTES;
#pragma unroll
        for (int ks = 0; ks < 4; ks++) {
            int kb = ks * 16;
            uint32_t af[2][4], gf[2][4], uf[2][4];
#pragma unroll
            for (int mt = 0; mt < 2; mt++) {
                uint32_t ro = (uint32_t)(((wm * 32 + mt * 16 + a_lr) * RS64 + kb + a_lk) * 2);
                ldsm4(af[mt], bb + G1_A * 2 + ro);
            }
#pragma unroll
            for (int ntp = 0; ntp < 2; ntp++) {
                uint32_t ro = (uint32_t)(((wn * 32 + ntp * 16 + b_lr) * RS64 + kb + b_lk) * 2);
                ldsm4(gf[ntp], bb + G1_G * 2 + ro);
                ldsm4(uf[ntp], bb + G1_U * 2 + ro);
            }
#pragma unroll
            for (int ntp = 0; ntp < 2; ntp++)
#pragma unroll
                for (int sub = 0; sub < 2; sub++) {
                    int nt = ntp * 2 + sub;
                    uint32_t bg[2] = {gf[ntp][sub * 2], gf[ntp][sub * 2 + 1]};
                    uint32_t bu[2] = {uf[ntp][sub * 2], uf[ntp][sub * 2 + 1]};
#pragma unroll
                    for (int mt = 0; mt < 2; mt++) {
                        mma_f16(dg[mt][nt], af[mt], bg);
                        mma_f16(du[mt][nt], af[mt], bu);
                    }
                }
        }
    }

    int gi = lid >> 2, tg = lid & 3;
#pragma unroll
    for (int mt = 0; mt < 2; mt++) {
        size_t rr = (size_t)(mbase + wm * 32 + mt * 16 + gi);
#pragma unroll
        for (int nt = 0; nt < 4; nt++) {
            int col = nbase + wn * 32 + nt * 8 + tg * 2;
            float h00 = silu(dg[mt][nt][0]) * du[mt][nt][0];
            float h01 = silu(dg[mt][nt][1]) * du[mt][nt][1];
            float h10 = silu(dg[mt][nt][2]) * du[mt][nt][2];
            float h11 = silu(dg[mt][nt][3]) * du[mt][nt][3];
            *reinterpret_cast<uint32_t*>(g_hf + rr * IDIM + col)       = pack2h(h00, h01);
            *reinterpret_cast<uint32_t*>(g_hf + (rr + 8) * IDIM + col) = pack2h(h10, h11);
        }
    }
}

// ---------------- GEMM2: out[tok] += wt * (h W2^T) ----------------
// (R11 config, proven) CTA 128M x 64N, 8 warps (32x32), BK=32, 4-stage, 3 CTAs/SM.
constexpr int G2_A = 0, G2_B = 128 * RS;
constexpr uint32_t G2_STAGE_BYTES = 192 * RS * 2;    // 15360
constexpr size_t SMEM2 = 4 * (size_t)G2_STAGE_BYTES; // 61440 -> 3 CTAs/SM

__global__ __launch_bounds__(256, 3)
void gemm2_kernel(float* __restrict__ out) {
    extern __shared__ __align__(16) char dsm[];
    uint32_t smemB = smem_u32(dsm);

    int mbase = blockIdx.y * 128;
    int nbase = blockIdx.x * 64;
    if (mbase >= g_off[E]) return;
    int e = 0;
    while (e < E && !(mbase >= g_off[e] && mbase < g_off[e + 1])) e++;

    int tid = threadIdx.x, lid = tid & 31, wid = tid >> 5;
    int wm = wid & 3, wn = wid >> 2;

    int crow = tid >> 2, cch = tid & 3;
    const __half* sA0 = g_hf + (size_t)(mbase + crow) * IDIM + cch * 8;
    const __half* sA1 = sA0 + (size_t)64 * IDIM;
    size_t wrow = ((size_t)e * H + nbase + crow) * IDIM + cch * 8;
    const __half* sB = g_w2f + wrow;

    uint32_t dA0 = (uint32_t)((G2_A + crow * RS) * 2 + cch * 16);
    uint32_t dA1 = dA0 + 64 * RS * 2;
    uint32_t dB  = (uint32_t)((G2_B + crow * RS) * 2 + cch * 16);

    auto issue = [&](int s, int k0) {
        uint32_t sb = smemB + (uint32_t)s * G2_STAGE_BYTES;
        cp16(sb + dA0, sA0 + k0);
        cp16(sb + dA1, sA1 + k0);
        cp16(sb + dB,  sB + k0);
    };

    int a_lr = (lid & 7) + ((lid >> 3) & 1) * 8, a_lk = ((lid >> 4) & 1) * 8;
    int b_lr = (lid & 7) + ((lid >> 4) & 1) * 8, b_lk = ((lid >> 3) & 1) * 8;

    float d[2][4][4] = {};

    issue(0, 0);   CP_COMMIT();
    issue(1, 32);  CP_COMMIT();
    issue(2, 64);  CP_COMMIT();

    constexpr int NCH = IDIM / 32; // 88
    for (int c = 0; c < NCH; c++) {
        CP_WAIT2();
        __syncthreads();
        if (c + 3 < NCH) issue((c + 3) & 3, (c + 3) * 32);
        CP_COMMIT();
        uint32_t bb = smemB + (uint32_t)(c & 3) * G2_STAGE_BYTES;
#pragma unroll
        for (int ks = 0; ks < 2; ks++) {
            int kb = ks * 16;
            uint32_t af[2][4], bf[2][4];
#pragma unroll
            for (int mt = 0; mt < 2; mt++) {
                uint32_t ro = (uint32_t)(((wm * 32 + mt * 16 + a_lr) * RS + kb + a_lk) * 2);
                ldsm4(af[mt], bb + G2_A * 2 + ro);
            }
#pragma unroll
            for (int ntp = 0; ntp < 2; ntp++) {
                uint32_t ro = (uint32_t)(((wn * 32 + ntp * 16 + b_lr) * RS + kb + b_lk) * 2);
                ldsm4(bf[ntp], bb + G2_B * 2 + ro);
            }
#pragma unroll
            for (int ntp = 0; ntp < 2; ntp++)
#pragma unroll
                for (int sub = 0; sub < 2; sub++) {
                    int nt = ntp * 2 + sub;
                    uint32_t b_[2] = {bf[ntp][sub * 2], bf[ntp][sub * 2 + 1]};
#pragma unroll
                    for (int mt = 0; mt < 2; mt++)
                        mma_f16(d[mt][nt], af[mt], b_);
                }
        }
    }

    // epilogue: fused top-2 combine via atomicAdd
    int gi = lid >> 2, tg = lid & 3;
#pragma unroll
    for (int mt = 0; mt < 2; mt++) {
        int rr = mbase + wm * 32 + mt * 16 + gi;
        int t0 = g_slot_token[rr];
        int t1 = g_slot_token[rr + 8];
        float w0 = (t0 >= 0) ? g_slot_wt[rr] : 0.0f;
        float w1 = (t1 >= 0) ? g_slot_wt[rr + 8] : 0.0f;
#pragma unroll
        for (int nt = 0; nt < 4; nt++) {
            int col = nbase + wn * 32 + nt * 8 + tg * 2;
            if (t0 >= 0) {
                atomicAdd(out + (size_t)t0 * H + col,     w0 * d[mt][nt][0]);
                atomicAdd(out + (size_t)t0 * H + col + 1, w0 * d[mt][nt][1]);
            }
            if (t1 >= 0) {
                atomicAdd(out + (size_t)t1 * H + col,     w1 * d[mt][nt][2]);
                atomicAdd(out + (size_t)t1 * H + col + 1, w1 * d[mt][nt][3]);
            }
        }
    }
}

// ---------------- entry ----------------
extern "C" void kernel_launch(void* const* d_in, const int* in_sizes, int n_in,
                              void* d_out, int out_size) {
    const float* x      = (const float*)d_in[0];
    const float* logits = (const float*)d_in[1];
    const float* W1     = (const float*)d_in[2];
    const float* W3     = (const float*)d_in[3];
    const float* W2     = (const float*)d_in[4];
    float* out          = (float*)d_out;

    cudaFuncSetAttribute(gemm1_kernel, cudaFuncAttributeMaxDynamicSharedMemorySize, (int)SMEM1);
    cudaFuncSetAttribute(gemm2_kernel, cudaFuncAttributeMaxDynamicSharedMemorySize, (int)SMEM2);

    init_route_kernel<<<(MAX_SLOTS + 255) / 256, 256>>>(logits);               // 0
    scan_assign_kernel<<<1, 256>>>();                                          // 1
    cvt_all_kernel<<<3 * WB + XB, 256>>>((const float4*)W1, (const float4*)W3,
                                         (const float4*)W2, (const float4*)x); // 2
    dim3 g1(IDIM / 64, MAX_SLOTS / 128);
    gemm1_kernel<<<g1, 256, SMEM1>>>();                                        // 3 <- ncu profiles this

    zero_out_kernel<<<(T * H / 4) / 256, 256>>>((float4*)out);                 // 4

    dim3 g2(H / 64, MAX_SLOTS / 128);
    gemm2_kernel<<<g2, 256, SMEM2>>>(out);                                     // 5
}

// round 16
// speedup vs baseline: 1.3148x; 1.3148x over previous
#include <cuda_runtime.h>
#include <cuda_fp16.h>
#include <math.h>
#include <cstdint>

// ---------------- problem constants ----------------
constexpr int T    = 2048;
constexpr int H    = 1024;
constexpr int IDIM = 2816;
constexpr int E    = 8;
constexpr int TOPK = 2;

constexpr int BMT = 128;
constexpr int MAX_SLOTS = T * TOPK + E * BMT;  // 5120
constexpr int RS64 = 72;  // BK=64 row stride (halfs), 144B

constexpr size_t WELEMS = (size_t)E * IDIM * H;
constexpr int WN4 = (int)(WELEMS / 4);
constexpr int XN4 = T * H / 4;

// ---------------- scratch ----------------
__device__ int   g_off[E + 1];
__device__ int   g_slot_token[MAX_SLOTS];
__device__ float g_slot_wt[MAX_SLOTS];
__device__ int   g_top_id[T * TOPK];
__device__ float g_top_w[T * TOPK];

__device__ __align__(16) __half g_w1f[WELEMS];
__device__ __align__(16) __half g_w3f[WELEMS];
__device__ __align__(16) __half g_w2f[WELEMS];
__device__ __align__(16) __half g_xf[T * H];
__device__ __align__(16) __half g_hf[(size_t)MAX_SLOTS * IDIM];

// ---------------- PTX helpers ----------------
__device__ __forceinline__ uint32_t smem_u32(const void* p) {
    uint32_t a;
    asm("{ .reg .u64 t; cvta.to.shared.u64 t, %1; cvt.u32.u64 %0, t; }" : "=r"(a) : "l"(p));
    return a;
}
__device__ __forceinline__ void cp16(uint32_t dst, const void* src) {
    asm volatile("cp.async.cg.shared.global [%0], [%1], 16;" :: "r"(dst), "l"(src));
}
#define CP_COMMIT() asm volatile("cp.async.commit_group;" ::: "memory")
#define CP_WAIT1()  asm volatile("cp.async.wait_group 1;" ::: "memory")

__device__ __forceinline__ void ldsm4(uint32_t r[4], uint32_t addr) {
    asm volatile("ldmatrix.sync.aligned.m8n8.x4.shared.b16 {%0,%1,%2,%3}, [%4];"
        : "=r"(r[0]), "=r"(r[1]), "=r"(r[2]), "=r"(r[3]) : "r"(addr));
}
__device__ __forceinline__ void mma_f16(float d[4], const uint32_t a[4], const uint32_t b[2]) {
    asm volatile(
        "mma.sync.aligned.m16n8k16.row.col.f32.f16.f16.f32 "
        "{%0,%1,%2,%3}, {%4,%5,%6,%7}, {%8,%9}, {%0,%1,%2,%3};"
        : "+f"(d[0]), "+f"(d[1]), "+f"(d[2]), "+f"(d[3])
        : "r"(a[0]), "r"(a[1]), "r"(a[2]), "r"(a[3]), "r"(b[0]), "r"(b[1]));
}
__device__ __forceinline__ uint32_t pack2h(float a, float b) {
    __half2 v;
    v.x = __float2half_rn(a);
    v.y = __float2half_rn(b);
    return *reinterpret_cast<uint32_t*>(&v);
}
__device__ __forceinline__ float silu(float g) { return g / (1.0f + __expf(-g)); }

// ---------------- launch 0: init + route ----------------
__global__ void init_route_kernel(const float* __restrict__ logits) {
    int i = blockIdx.x * blockDim.x + threadIdx.x;
    if (i < MAX_SLOTS) g_slot_token[i] = -1;
    if (i >= T) return;
    const float* lg = logits + (size_t)i * E;
    float l[E];
#pragma unroll
    for (int e = 0; e < E; e++) l[e] = lg[e];
    int a = 0; float la = l[0];
#pragma unroll
    for (int e = 1; e < E; e++) if (l[e] > la) { la = l[e]; a = e; }
    int b = -1; float lb = -INFINITY;
#pragma unroll
    for (int e = 0; e < E; e++) if (e != a && l[e] > lb) { lb = l[e]; b = e; }
    float w0 = 1.0f / (1.0f + expf(lb - la));
    g_top_id[i * 2 + 0] = a; g_top_w[i * 2 + 0] = w0;
    g_top_id[i * 2 + 1] = b; g_top_w[i * 2 + 1] = 1.0f - w0;
}

// ---------------- launch 1: count + scan + assign ----------------
__global__ void scan_assign_kernel() {
    __shared__ int cnt[E];
    __shared__ int cur[E];
    int tid = threadIdx.x;
    if (tid < E) cnt[tid] = 0;
    __syncthreads();
    for (int i = tid; i < T * TOPK; i += blockDim.x)
        atomicAdd(&cnt[g_top_id[i]], 1);
    __syncthreads();
    if (tid == 0) {
        int off = 0;
        for (int e = 0; e < E; e++) {
            g_off[e] = off; cur[e] = off;
            off += ((cnt[e] + BMT - 1) / BMT) * BMT;
        }
        g_off[E] = off;
    }
    __syncthreads();
    for (int i = tid; i < T * TOPK; i += blockDim.x) {
        int e = g_top_id[i];
        int pos = atomicAdd(&cur[e], 1);
        g_slot_token[pos] = i >> 1;
        g_slot_wt[pos] = g_top_w[i];
    }
}

// ---------------- launch 2: merged fp32->fp16 converter ----------------
constexpr int WB = WN4 / 256;
constexpr int XB = XN4 / 256;
__device__ __forceinline__ void cvt_single(const float4* __restrict__ src, __half* dst, int b) {
    int i = b * 256 + threadIdx.x;
    float4 v = src[i];
    reinterpret_cast<uint2*>(dst)[i] = make_uint2(pack2h(v.x, v.y), pack2h(v.z, v.w));
}
__global__ void cvt_all_kernel(const float4* __restrict__ W1, const float4* __restrict__ W3,
                               const float4* __restrict__ W2, const float4* __restrict__ x) {
    int b = blockIdx.x;
    if      (b < WB)          cvt_single(W1, g_w1f, b);
    else if (b < 2 * WB)      cvt_single(W3, g_w3f, b - WB);
    else if (b < 3 * WB)      cvt_single(W2, g_w2f, b - 2 * WB);
    else                      cvt_single(x, g_xf, b - 3 * WB);
}

__global__ void zero_out_kernel(float4* out) {
    out[blockIdx.x * 256 + threadIdx.x] = make_float4(0.f, 0.f, 0.f, 0.f);
}

// ---------------- GEMM1: h = silu(x W1^T) * (x W3^T) ----------------
// (R13 winner, frozen) CTA 128M x 64N, 8 warps (32x32), BK=64, 3-stage, coalesced copies.
constexpr int G1_A = 0, G1_G = 128 * RS64, G1_U = 192 * RS64;
constexpr uint32_t G1_STAGE_BYTES = 256 * RS64 * 2;   // 36864
constexpr size_t SMEM1 = 3 * (size_t)G1_STAGE_BYTES;  // 110592/CTA -> 2 CTAs/SM

__global__ __launch_bounds__(256, 2)
void gemm1_kernel() {
    extern __shared__ __align__(16) char dsm[];
    uint32_t smemB = smem_u32(dsm);

    int mbase = blockIdx.y * 128;
    int nbase = blockIdx.x * 64;
    if (mbase >= g_off[E]) return;
    int e = 0;
    while (e < E && !(mbase >= g_off[e] && mbase < g_off[e + 1])) e++;

    int tid = threadIdx.x, lid = tid & 31, wid = tid >> 5;
    int wm = wid & 3, wn = wid >> 2;

    int r0 = tid >> 3, cch = tid & 7;
    int tk[4];
#pragma unroll
    for (int j = 0; j < 4; j++) {
        int t = g_slot_token[mbase + r0 + 32 * j];
        tk[j] = (t < 0) ? 0 : t;
    }
    const __half* gp = g_w1f + ((size_t)e * IDIM + nbase + r0) * H + cch * 8;
    const __half* up = g_w3f + ((size_t)e * IDIM + nbase + r0) * H + cch * 8;

    uint32_t rdst = (uint32_t)(r0 * RS64 * 2 + cch * 16);

    auto issue = [&](int s, int k0) {
        uint32_t sb = smemB + (uint32_t)s * G1_STAGE_BYTES + rdst;
#pragma unroll
        for (int j = 0; j < 4; j++)
            cp16(sb + (uint32_t)(32 * j * RS64 * 2),
                 g_xf + (size_t)tk[j] * H + k0 + cch * 8);
#pragma unroll
        for (int j = 0; j < 2; j++)
            cp16(sb + (uint32_t)((128 + 32 * j) * RS64 * 2), gp + (size_t)(32 * j) * H + k0);
#pragma unroll
        for (int j = 0; j < 2; j++)
            cp16(sb + (uint32_t)((192 + 32 * j) * RS64 * 2), up + (size_t)(32 * j) * H + k0);
    };

    int a_lr = (lid & 7) + ((lid >> 3) & 1) * 8, a_lk = ((lid >> 4) & 1) * 8;
    int b_lr = (lid & 7) + ((lid >> 4) & 1) * 8, b_lk = ((lid >> 3) & 1) * 8;

    float dg[2][4][4] = {}, du[2][4][4] = {};

    issue(0, 0);  CP_COMMIT();
    issue(1, 64); CP_COMMIT();

    constexpr int NCH = H / 64; // 16
    for (int c = 0; c < NCH; c++) {
        CP_WAIT1();
        __syncthreads();
        if (c + 2 < NCH) issue((c + 2) % 3, (c + 2) * 64);
        CP_COMMIT();
        uint32_t bb = smemB + (uint32_t)(c % 3) * G1_STAGE_BYTES;
#pragma unroll
        for (int ks = 0; ks < 4; ks++) {
            int kb = ks * 16;
            uint32_t af[2][4], gf[2][4], uf[2][4];
#pragma unroll
            for (int mt = 0; mt < 2; mt++) {
                uint32_t ro = (uint32_t)(((wm * 32 + mt * 16 + a_lr) * RS64 + kb + a_lk) * 2);
                ldsm4(af[mt], bb + G1_A * 2 + ro);
            }
#pragma unroll
            for (int ntp = 0; ntp < 2; ntp++) {
                uint32_t ro = (uint32_t)(((wn * 32 + ntp * 16 + b_lr) * RS64 + kb + b_lk) * 2);
                ldsm4(gf[ntp], bb + G1_G * 2 + ro);
                ldsm4(uf[ntp], bb + G1_U * 2 + ro);
            }
#pragma unroll
            for (int ntp = 0; ntp < 2; ntp++)
#pragma unroll
                for (int sub = 0; sub < 2; sub++) {
                    int nt = ntp * 2 + sub;
                    uint32_t bg[2] = {gf[ntp][sub * 2], gf[ntp][sub * 2 + 1]};
                    uint32_t bu[2] = {uf[ntp][sub * 2], uf[ntp][sub * 2 + 1]};
#pragma unroll
                    for (int mt = 0; mt < 2; mt++) {
                        mma_f16(dg[mt][nt], af[mt], bg);
                        mma_f16(du[mt][nt], af[mt], bu);
                    }
                }
        }
    }

    int gi = lid >> 2, tg = lid & 3;
#pragma unroll
    for (int mt = 0; mt < 2; mt++) {
        size_t rr = (size_t)(mbase + wm * 32 + mt * 16 + gi);
#pragma unroll
        for (int nt = 0; nt < 4; nt++) {
            int col = nbase + wn * 32 + nt * 8 + tg * 2;
            float h00 = silu(dg[mt][nt][0]) * du[mt][nt][0];
            float h01 = silu(dg[mt][nt][1]) * du[mt][nt][1];
            float h10 = silu(dg[mt][nt][2]) * du[mt][nt][2];
            float h11 = silu(dg[mt][nt][3]) * du[mt][nt][3];
            *reinterpret_cast<uint32_t*>(g_hf + rr * IDIM + col)       = pack2h(h00, h01);
            *reinterpret_cast<uint32_t*>(g_hf + (rr + 8) * IDIM + col) = pack2h(h10, h11);
        }
    }
}

// ---------------- GEMM2: out[tok] += wt * (h W2^T) ----------------
// NEW: clone of R13-gemm1 shape. CTA 128M x 128N, 8 warps (warp 32Mx64N),
// BK=64, 3-stage, coalesced copies. Grid 40x8 = 320 CTAs (1.08 waves at 2/SM).
// stage rows: A[128] B[128], each row RS64 halfs.
constexpr int G2_A = 0, G2_B = 128 * RS64;
constexpr uint32_t G2_STAGE_BYTES = 256 * RS64 * 2;   // 36864
constexpr size_t SMEM2 = 3 * (size_t)G2_STAGE_BYTES;  // 110592/CTA -> 2 CTAs/SM

__global__ __launch_bounds__(256, 2)
void gemm2_kernel(float* __restrict__ out) {
    extern __shared__ __align__(16) char dsm[];
    uint32_t smemB = smem_u32(dsm);

    int mbase = blockIdx.y * 128;
    int nbase = blockIdx.x * 128;
    if (mbase >= g_off[E]) return;
    int e = 0;
    while (e < E && !(mbase >= g_off[e] && mbase < g_off[e + 1])) e++;

    int tid = threadIdx.x, lid = tid & 31, wid = tid >> 5;
    int wm = wid & 3, wn = wid >> 2;  // warp: rows wm*32..+32, cols wn*64..+64

    // coalesced copies: r0 = tid>>3, cch = tid&7; 8 rows/thread:
    //   A rows r0+32j (j=0..3) from g_hf; B rows r0+32j (j=0..3) from g_w2f
    int r0 = tid >> 3, cch = tid & 7;
    const __half* ap = g_hf + (size_t)(mbase + r0) * IDIM + cch * 8;
    const __half* bp = g_w2f + ((size_t)e * H + nbase + r0) * IDIM + cch * 8;

    uint32_t rdst = (uint32_t)(r0 * RS64 * 2 + cch * 16);

    auto issue = [&](int s, int k0) {
        uint32_t sb = smemB + (uint32_t)s * G2_STAGE_BYTES + rdst;
#pragma unroll
        for (int j = 0; j < 4; j++)
            cp16(sb + (uint32_t)(32 * j * RS64 * 2), ap + (size_t)(32 * j) * IDIM + k0);
#pragma unroll
        for (int j = 0; j < 4; j++)
            cp16(sb + (uint32_t)((128 + 32 * j) * RS64 * 2), bp + (size_t)(32 * j) * IDIM + k0);
    };

    int a_lr = (lid & 7) + ((lid >> 3) & 1) * 8, a_lk = ((lid >> 4) & 1) * 8;
    int b_lr = (lid & 7) + ((lid >> 4) & 1) * 8, b_lk = ((lid >> 3) & 1) * 8;

    float d[2][8][4] = {};   // [mt][n8][4] = 64 accum

    issue(0, 0);  CP_COMMIT();
    issue(1, 64); CP_COMMIT();

    constexpr int NCH = IDIM / 64; // 44
    for (int c = 0; c < NCH; c++) {
        CP_WAIT1();
        __syncthreads();
        if (c + 2 < NCH) issue((c + 2) % 3, (c + 2) * 64);
        CP_COMMIT();
        uint32_t bb = smemB + (uint32_t)(c % 3) * G2_STAGE_BYTES;
#pragma unroll
        for (int ks = 0; ks < 4; ks++) {
            int kb = ks * 16;
            uint32_t af[2][4], bf[4][4];
#pragma unroll
            for (int mt = 0; mt < 2; mt++) {
                uint32_t ro = (uint32_t)(((wm * 32 + mt * 16 + a_lr) * RS64 + kb + a_lk) * 2);
                ldsm4(af[mt], bb + G2_A * 2 + ro);
            }
#pragma unroll
            for (int ntp = 0; ntp < 4; ntp++) {
                uint32_t ro = (uint32_t)(((wn * 64 + ntp * 16 + b_lr) * RS64 + kb + b_lk) * 2);
                ldsm4(bf[ntp], bb + G2_B * 2 + ro);
            }
#pragma unroll
            for (int ntp = 0; ntp < 4; ntp++)
#pragma unroll
                for (int sub = 0; sub < 2; sub++) {
                    int nt = ntp * 2 + sub;
                    uint32_t b_[2] = {bf[ntp][sub * 2], bf[ntp][sub * 2 + 1]};
#pragma unroll
                    for (int mt = 0; mt < 2; mt++)
                        mma_f16(d[mt][nt], af[mt], b_);
                }
        }
    }

    // epilogue: fused top-2 combine via atomicAdd
    int gi = lid >> 2, tg = lid & 3;
#pragma unroll
    for (int mt = 0; mt < 2; mt++) {
        int rr = mbase + wm * 32 + mt * 16 + gi;
        int t0 = g_slot_token[rr];
        int t1 = g_slot_token[rr + 8];
        float w0 = (t0 >= 0) ? g_slot_wt[rr] : 0.0f;
        float w1 = (t1 >= 0) ? g_slot_wt[rr + 8] : 0.0f;
#pragma unroll
        for (int nt = 0; nt < 8; nt++) {
            int col = nbase + wn * 64 + nt * 8 + tg * 2;
            if (t0 >= 0) {
                atomicAdd(out + (size_t)t0 * H + col,     w0 * d[mt][nt][0]);
                atomicAdd(out + (size_t)t0 * H + col + 1, w0 * d[mt][nt][1]);
            }
            if (t1 >= 0) {
                atomicAdd(out + (size_t)t1 * H + col,     w1 * d[mt][nt][2]);
                atomicAdd(out + (size_t)t1 * H + col + 1, w1 * d[mt][nt][3]);
            }
        }
    }
}

// ---------------- entry ----------------
extern "C" void kernel_launch(void* const* d_in, const int* in_sizes, int n_in,
                              void* d_out, int out_size) {
    const float* x      = (const float*)d_in[0];
    const float* logits = (const float*)d_in[1];
    const float* W1     = (const float*)d_in[2];
    const float* W3     = (const float*)d_in[3];
    const float* W2     = (const float*)d_in[4];
    float* out          = (float*)d_out;

    cudaFuncSetAttribute(gemm1_kernel, cudaFuncAttributeMaxDynamicSharedMemorySize, (int)SMEM1);
    cudaFuncSetAttribute(gemm2_kernel, cudaFuncAttributeMaxDynamicSharedMemorySize, (int)SMEM2);

    init_route_kernel<<<(MAX_SLOTS + 255) / 256, 256>>>(logits);               // 0
    scan_assign_kernel<<<1, 256>>>();                                          // 1
    cvt_all_kernel<<<3 * WB + XB, 256>>>((const float4*)W1, (const float4*)W3,
                                         (const float4*)W2, (const float4*)x); // 2
    dim3 g1(IDIM / 64, MAX_SLOTS / 128);
    gemm1_kernel<<<g1, 256, SMEM1>>>();                                        // 3 <- ncu profiles this

    zero_out_kernel<<<(T * H / 4) / 256, 256>>>((float4*)out);                 // 4

    dim3 g2(H / 128, MAX_SLOTS / 128);
    gemm2_kernel<<<g2, 256, SMEM2>>>(out);                                     // 5
}

// round 17
// speedup vs baseline: 1.4438x; 1.0981x over previous
#include <cuda_runtime.h>
#include <cuda_fp16.h>
#include <math.h>
#include <cstdint>

// ---------------- problem constants ----------------
constexpr int T    = 2048;
constexpr int H    = 1024;
constexpr int IDIM = 2816;
constexpr int E    = 8;
constexpr int TOPK = 2;

constexpr int BMT = 128;
constexpr int MAX_SLOTS = T * TOPK + E * BMT;  // 5120
constexpr int RS64 = 72;  // BK=64 row stride (halfs), 144B

constexpr size_t WELEMS = (size_t)E * IDIM * H;
constexpr int WN4 = (int)(WELEMS / 4);
constexpr int XN4 = T * H / 4;

// ---------------- scratch ----------------
__device__ int   g_off[E + 1];
__device__ int   g_slot_token[MAX_SLOTS];
__device__ float g_slot_wt[MAX_SLOTS];
__device__ int   g_top_id[T * TOPK];
__device__ float g_top_w[T * TOPK];

__device__ __align__(16) __half g_w1f[WELEMS];
__device__ __align__(16) __half g_w3f[WELEMS];
__device__ __align__(16) __half g_w2f[WELEMS];
__device__ __align__(16) __half g_xf[T * H];
__device__ __align__(16) __half g_hf[(size_t)MAX_SLOTS * IDIM];

// ---------------- PTX helpers ----------------
__device__ __forceinline__ uint32_t smem_u32(const void* p) {
    uint32_t a;
    asm("{ .reg .u64 t; cvta.to.shared.u64 t, %1; cvt.u32.u64 %0, t; }" : "=r"(a) : "l"(p));
    return a;
}
__device__ __forceinline__ void cp16(uint32_t dst, const void* src) {
    asm volatile("cp.async.cg.shared.global [%0], [%1], 16;" :: "r"(dst), "l"(src));
}
#define CP_COMMIT() asm volatile("cp.async.commit_group;" ::: "memory")
#define CP_WAIT1()  asm volatile("cp.async.wait_group 1;" ::: "memory")

__device__ __forceinline__ void ldsm4(uint32_t r[4], uint32_t addr) {
    asm volatile("ldmatrix.sync.aligned.m8n8.x4.shared.b16 {%0,%1,%2,%3}, [%4];"
        : "=r"(r[0]), "=r"(r[1]), "=r"(r[2]), "=r"(r[3]) : "r"(addr));
}
__device__ __forceinline__ void mma_f16(float d[4], const uint32_t a[4], const uint32_t b[2]) {
    asm volatile(
        "mma.sync.aligned.m16n8k16.row.col.f32.f16.f16.f32 "
        "{%0,%1,%2,%3}, {%4,%5,%6,%7}, {%8,%9}, {%0,%1,%2,%3};"
        : "+f"(d[0]), "+f"(d[1]), "+f"(d[2]), "+f"(d[3])
        : "r"(a[0]), "r"(a[1]), "r"(a[2]), "r"(a[3]), "r"(b[0]), "r"(b[1]));
}
__device__ __forceinline__ uint32_t pack2h(float a, float b) {
    __half2 v;
    v.x = __float2half_rn(a);
    v.y = __float2half_rn(b);
    return *reinterpret_cast<uint32_t*>(&v);
}
__device__ __forceinline__ float silu(float g) { return g / (1.0f + __expf(-g)); }

// ---------------- init + route ----------------
__global__ void init_route_kernel(const float* __restrict__ logits) {
    int i = blockIdx.x * blockDim.x + threadIdx.x;
    if (i < MAX_SLOTS) g_slot_token[i] = -1;
    if (i >= T) return;
    const float* lg = logits + (size_t)i * E;
    float l[E];
#pragma unroll
    for (int e = 0; e < E; e++) l[e] = lg[e];
    int a = 0; float la = l[0];
#pragma unroll
    for (int e = 1; e < E; e++) if (l[e] > la) { la = l[e]; a = e; }
    int b = -1; float lb = -INFINITY;
#pragma unroll
    for (int e = 0; e < E; e++) if (e != a && l[e] > lb) { lb = l[e]; b = e; }
    float w0 = 1.0f / (1.0f + expf(lb - la));
    g_top_id[i * 2 + 0] = a; g_top_w[i * 2 + 0] = w0;
    g_top_id[i * 2 + 1] = b; g_top_w[i * 2 + 1] = 1.0f - w0;
}

// ---------------- count + scan + assign ----------------
__global__ void scan_assign_kernel() {
    __shared__ int cnt[E];
    __shared__ int cur[E];
    int tid = threadIdx.x;
    if (tid < E) cnt[tid] = 0;
    __syncthreads();
    for (int i = tid; i < T * TOPK; i += blockDim.x)
        atomicAdd(&cnt[g_top_id[i]], 1);
    __syncthreads();
    if (tid == 0) {
        int off = 0;
        for (int e = 0; e < E; e++) {
            g_off[e] = off; cur[e] = off;
            off += ((cnt[e] + BMT - 1) / BMT) * BMT;
        }
        g_off[E] = off;
    }
    __syncthreads();
    for (int i = tid; i < T * TOPK; i += blockDim.x) {
        int e = g_top_id[i];
        int pos = atomicAdd(&cur[e], 1);
        g_slot_token[pos] = i >> 1;
        g_slot_wt[pos] = g_top_w[i];
    }
}

// ---------------- converters ----------------
constexpr int WB = WN4 / 256;
constexpr int XB = XN4 / 256;
__device__ __forceinline__ void cvt_single(const float4* __restrict__ src, __half* dst, int b) {
    int i = b * 256 + threadIdx.x;
    float4 v = src[i];
    reinterpret_cast<uint2*>(dst)[i] = make_uint2(pack2h(v.x, v.y), pack2h(v.z, v.w));
}
// main-stream converter: W1, W3, x (gemm1's inputs)
__global__ void cvt_w13x_kernel(const float4* __restrict__ W1, const float4* __restrict__ W3,
                                const float4* __restrict__ x) {
    int b = blockIdx.x;
    if      (b < WB)      cvt_single(W1, g_w1f, b);
    else if (b < 2 * WB)  cvt_single(W3, g_w3f, b - WB);
    else                  cvt_single(x, g_xf, b - 2 * WB);
}
// side-stream converter: W2 (only needed by gemm2)
__global__ void cvt_w2_kernel(const float4* __restrict__ W2) {
    cvt_single(W2, g_w2f, blockIdx.x);
}

__global__ void zero_out_kernel(float4* out) {
    out[blockIdx.x * 256 + threadIdx.x] = make_float4(0.f, 0.f, 0.f, 0.f);
}

// ---------------- GEMM1 (R13 winner, frozen) ----------------
constexpr int G1_A = 0, G1_G = 128 * RS64, G1_U = 192 * RS64;
constexpr uint32_t G1_STAGE_BYTES = 256 * RS64 * 2;   // 36864
constexpr size_t SMEM1 = 3 * (size_t)G1_STAGE_BYTES;  // 110592/CTA -> 2 CTAs/SM

__global__ __launch_bounds__(256, 2)
void gemm1_kernel() {
    extern __shared__ __align__(16) char dsm[];
    uint32_t smemB = smem_u32(dsm);

    int mbase = blockIdx.y * 128;
    int nbase = blockIdx.x * 64;
    if (mbase >= g_off[E]) return;
    int e = 0;
    while (e < E && !(mbase >= g_off[e] && mbase < g_off[e + 1])) e++;

    int tid = threadIdx.x, lid = tid & 31, wid = tid >> 5;
    int wm = wid & 3, wn = wid >> 2;

    int r0 = tid >> 3, cch = tid & 7;
    int tk[4];
#pragma unroll
    for (int j = 0; j < 4; j++) {
        int t = g_slot_token[mbase + r0 + 32 * j];
        tk[j] = (t < 0) ? 0 : t;
    }
    const __half* gp = g_w1f + ((size_t)e * IDIM + nbase + r0) * H + cch * 8;
    const __half* up = g_w3f + ((size_t)e * IDIM + nbase + r0) * H + cch * 8;

    uint32_t rdst = (uint32_t)(r0 * RS64 * 2 + cch * 16);

    auto issue = [&](int s, int k0) {
        uint32_t sb = smemB + (uint32_t)s * G1_STAGE_BYTES + rdst;
#pragma unroll
        for (int j = 0; j < 4; j++)
            cp16(sb + (uint32_t)(32 * j * RS64 * 2),
                 g_xf + (size_t)tk[j] * H + k0 + cch * 8);
#pragma unroll
        for (int j = 0; j < 2; j++)
            cp16(sb + (uint32_t)((128 + 32 * j) * RS64 * 2), gp + (size_t)(32 * j) * H + k0);
#pragma unroll
        for (int j = 0; j < 2; j++)
            cp16(sb + (uint32_t)((192 + 32 * j) * RS64 * 2), up + (size_t)(32 * j) * H + k0);
    };

    int a_lr = (lid & 7) + ((lid >> 3) & 1) * 8, a_lk = ((lid >> 4) & 1) * 8;
    int b_lr = (lid & 7) + ((lid >> 4) & 1) * 8, b_lk = ((lid >> 3) & 1) * 8;

    float dg[2][4][4] = {}, du[2][4][4] = {};

    issue(0, 0);  CP_COMMIT();
    issue(1, 64); CP_COMMIT();

    constexpr int NCH = H / 64; // 16
    for (int c = 0; c < NCH; c++) {
        CP_WAIT1();
        __syncthreads();
        if (c + 2 < NCH) issue((c + 2) % 3, (c + 2) * 64);
        CP_COMMIT();
        uint32_t bb = smemB + (uint32_t)(c % 3) * G1_STAGE_BYTES;
#pragma unroll
        for (int ks = 0; ks < 4; ks++) {
            int kb = ks * 16;
            uint32_t af[2][4], gf[2][4], uf[2][4];
#pragma unroll
            for (int mt = 0; mt < 2; mt++) {
                uint32_t ro = (uint32_t)(((wm * 32 + mt * 16 + a_lr) * RS64 + kb + a_lk) * 2);
                ldsm4(af[mt], bb + G1_A * 2 + ro);
            }
#pragma unroll
            for (int ntp = 0; ntp < 2; ntp++) {
                uint32_t ro = (uint32_t)(((wn * 32 + ntp * 16 + b_lr) * RS64 + kb + b_lk) * 2);
                ldsm4(gf[ntp], bb + G1_G * 2 + ro);
                ldsm4(uf[ntp], bb + G1_U * 2 + ro);
            }
#pragma unroll
            for (int ntp = 0; ntp < 2; ntp++)
#pragma unroll
                for (int sub = 0; sub < 2; sub++) {
                    int nt = ntp * 2 + sub;
                    uint32_t bg[2] = {gf[ntp][sub * 2], gf[ntp][sub * 2 + 1]};
                    uint32_t bu[2] = {uf[ntp][sub * 2], uf[ntp][sub * 2 + 1]};
#pragma unroll
                    for (int mt = 0; mt < 2; mt++) {
                        mma_f16(dg[mt][nt], af[mt], bg);
                        mma_f16(du[mt][nt], af[mt], bu);
                    }
                }
        }
    }

    int gi = lid >> 2, tg = lid & 3;
#pragma unroll
    for (int mt = 0; mt < 2; mt++) {
        size_t rr = (size_t)(mbase + wm * 32 + mt * 16 + gi);
#pragma unroll
        for (int nt = 0; nt < 4; nt++) {
            int col = nbase + wn * 32 + nt * 8 + tg * 2;
            float h00 = silu(dg[mt][nt][0]) * du[mt][nt][0];
            float h01 = silu(dg[mt][nt][1]) * du[mt][nt][1];
            float h10 = silu(dg[mt][nt][2]) * du[mt][nt][2];
            float h11 = silu(dg[mt][nt][3]) * du[mt][nt][3];
            *reinterpret_cast<uint32_t*>(g_hf + rr * IDIM + col)       = pack2h(h00, h01);
            *reinterpret_cast<uint32_t*>(g_hf + (rr + 8) * IDIM + col) = pack2h(h10, h11);
        }
    }
}

// ---------------- GEMM2 (R16 winner, frozen) ----------------
constexpr int G2_A = 0, G2_B = 128 * RS64;
constexpr uint32_t G2_STAGE_BYTES = 256 * RS64 * 2;   // 36864
constexpr size_t SMEM2 = 3 * (size_t)G2_STAGE_BYTES;  // 110592/CTA -> 2 CTAs/SM

__global__ __launch_bounds__(256, 2)
void gemm2_kernel(float* __restrict__ out) {
    extern __shared__ __align__(16) char dsm[];
    uint32_t smemB = smem_u32(dsm);

    int mbase = blockIdx.y * 128;
    int nbase = blockIdx.x * 128;
    if (mbase >= g_off[E]) return;
    int e = 0;
    while (e < E && !(mbase >= g_off[e] && mbase < g_off[e + 1])) e++;

    int tid = threadIdx.x, lid = tid & 31, wid = tid >> 5;
    int wm = wid & 3, wn = wid >> 2;

    int r0 = tid >> 3, cch = tid & 7;
    const __half* ap = g_hf + (size_t)(mbase + r0) * IDIM + cch * 8;
    const __half* bp = g_w2f + ((size_t)e * H + nbase + r0) * IDIM + cch * 8;

    uint32_t rdst = (uint32_t)(r0 * RS64 * 2 + cch * 16);

    auto issue = [&](int s, int k0) {
        uint32_t sb = smemB + (uint32_t)s * G2_STAGE_BYTES + rdst;
#pragma unroll
        for (int j = 0; j < 4; j++)
            cp16(sb + (uint32_t)(32 * j * RS64 * 2), ap + (size_t)(32 * j) * IDIM + k0);
#pragma unroll
        for (int j = 0; j < 4; j++)
            cp16(sb + (uint32_t)((128 + 32 * j) * RS64 * 2), bp + (size_t)(32 * j) * IDIM + k0);
    };

    int a_lr = (lid & 7) + ((lid >> 3) & 1) * 8, a_lk = ((lid >> 4) & 1) * 8;
    int b_lr = (lid & 7) + ((lid >> 4) & 1) * 8, b_lk = ((lid >> 3) & 1) * 8;

    float d[2][8][4] = {};

    issue(0, 0);  CP_COMMIT();
    issue(1, 64); CP_COMMIT();

    constexpr int NCH = IDIM / 64; // 44
    for (int c = 0; c < NCH; c++) {
        CP_WAIT1();
        __syncthreads();
        if (c + 2 < NCH) issue((c + 2) % 3, (c + 2) * 64);
        CP_COMMIT();
        uint32_t bb = smemB + (uint32_t)(c % 3) * G2_STAGE_BYTES;
#pragma unroll
        for (int ks = 0; ks < 4; ks++) {
            int kb = ks * 16;
            uint32_t af[2][4], bf[4][4];
#pragma unroll
            for (int mt = 0; mt < 2; mt++) {
                uint32_t ro = (uint32_t)(((wm * 32 + mt * 16 + a_lr) * RS64 + kb + a_lk) * 2);
                ldsm4(af[mt], bb + G2_A * 2 + ro);
            }
#pragma unroll
            for (int ntp = 0; ntp < 4; ntp++) {
                uint32_t ro = (uint32_t)(((wn * 64 + ntp * 16 + b_lr) * RS64 + kb + b_lk) * 2);
                ldsm4(bf[ntp], bb + G2_B * 2 + ro);
            }
#pragma unroll
            for (int ntp = 0; ntp < 4; ntp++)
#pragma unroll
                for (int sub = 0; sub < 2; sub++) {
                    int nt = ntp * 2 + sub;
                    uint32_t b_[2] = {bf[ntp][sub * 2], bf[ntp][sub * 2 + 1]};
#pragma unroll
                    for (int mt = 0; mt < 2; mt++)
                        mma_f16(d[mt][nt], af[mt], b_);
                }
        }
    }

    int gi = lid >> 2, tg = lid & 3;
#pragma unroll
    for (int mt = 0; mt < 2; mt++) {
        int rr = mbase + wm * 32 + mt * 16 + gi;
        int t0 = g_slot_token[rr];
        int t1 = g_slot_token[rr + 8];
        float w0 = (t0 >= 0) ? g_slot_wt[rr] : 0.0f;
        float w1 = (t1 >= 0) ? g_slot_wt[rr + 8] : 0.0f;
#pragma unroll
        for (int nt = 0; nt < 8; nt++) {
            int col = nbase + wn * 64 + nt * 8 + tg * 2;
            if (t0 >= 0) {
                atomicAdd(out + (size_t)t0 * H + col,     w0 * d[mt][nt][0]);
                atomicAdd(out + (size_t)t0 * H + col + 1, w0 * d[mt][nt][1]);
            }
            if (t1 >= 0) {
                atomicAdd(out + (size_t)t1 * H + col,     w1 * d[mt][nt][2]);
                atomicAdd(out + (size_t)t1 * H + col + 1, w1 * d[mt][nt][3]);
            }
        }
    }
}

// ---------------- entry: fork-join two-stream schedule ----------------
extern "C" void kernel_launch(void* const* d_in, const int* in_sizes, int n_in,
                              void* d_out, int out_size) {
    const float* x      = (const float*)d_in[0];
    const float* logits = (const float*)d_in[1];
    const float* W1     = (const float*)d_in[2];
    const float* W3     = (const float*)d_in[3];
    const float* W2     = (const float*)d_in[4];
    float* out          = (float*)d_out;

    cudaFuncSetAttribute(gemm1_kernel, cudaFuncAttributeMaxDynamicSharedMemorySize, (int)SMEM1);
    cudaFuncSetAttribute(gemm2_kernel, cudaFuncAttributeMaxDynamicSharedMemorySize, (int)SMEM2);

    // side stream + events (host ops; legal during capture; replay skips host code)
    cudaStream_t s1;
    cudaStreamCreate(&s1);
    cudaEvent_t eFork, eRoute, eSide;
    cudaEventCreateWithFlags(&eFork,  cudaEventDisableTiming);
    cudaEventCreateWithFlags(&eRoute, cudaEventDisableTiming);
    cudaEventCreateWithFlags(&eSide,  cudaEventDisableTiming);

    // fork s1 off the main (captured) stream
    cudaEventRecord(eFork, 0);
    cudaStreamWaitEvent(s1, eFork, 0);

    // main stream: convert gemm1's inputs (W1, W3, x)
    cvt_w13x_kernel<<<2 * WB + XB, 256>>>((const float4*)W1, (const float4*)W3,
                                          (const float4*)x);

    // side stream: routing, then zero(out) + convert W2 (overlaps gemm1)
    init_route_kernel<<<(MAX_SLOTS + 255) / 256, 256, 0, s1>>>(logits);
    scan_assign_kernel<<<1, 256, 0, s1>>>();
    cudaEventRecord(eRoute, s1);
    zero_out_kernel<<<(T * H / 4) / 256, 256, 0, s1>>>((float4*)out);
    cvt_w2_kernel<<<WB, 256, 0, s1>>>((const float4*)W2);
    cudaEventRecord(eSide, s1);

    // gemm1 needs cvt_w13x (in-order on stream 0) + routing tables
    cudaStreamWaitEvent(0, eRoute, 0);
    dim3 g1(IDIM / 64, MAX_SLOTS / 128);
    gemm1_kernel<<<g1, 256, SMEM1>>>();

    // gemm2 needs gemm1 (in-order) + W2 conversion + zeroed out
    cudaStreamWaitEvent(0, eSide, 0);
    dim3 g2(H / 128, MAX_SLOTS / 128);
    gemm2_kernel<<<g2, 256, SMEM2>>>(out);
}